// round 7
// baseline (speedup 1.0000x reference)
#include <cuda_runtime.h>

// Problem constants
#define B_   4
#define S_   8192
#define D_   512
#define P_   32
#define T_   (P_ + S_)          // 8224
#define EPS_ 1e-5f

#define NSB  256                 // s-blocks per batch for the reduction
#define ROWS_PER_SB (S_ / NSB)   // 32

// Scratch (allocation-free rule: __device__ globals)
__device__ __align__(16) float g_partial[B_][NSB][D_];   // 2 MB
__device__ __align__(16) float g_row[B_][D_];            // 8 KB

// ---------------------------------------------------------------------------
// Kernel 1: column-sum of x over a slice of S.  grid (NSB, B), block 128.
// Each thread owns one float4 column of D (128 float4 = 512 floats).
// 32 rows per block, fully unrolled -> deep independent LDG.128 pipeline.
// ---------------------------------------------------------------------------
__global__ void k_reduce(const float4* __restrict__ x4) {
    const int b  = blockIdx.y;
    const int sb = blockIdx.x;
    const int d4 = threadIdx.x;                 // 0..127
    const float4* p = x4 + ((size_t)b * S_ + (size_t)sb * ROWS_PER_SB) * (D_ / 4) + d4;
    float ax = 0.f, ay = 0.f, az = 0.f, aw = 0.f;
#pragma unroll
    for (int s = 0; s < ROWS_PER_SB; ++s) {
        float4 t = p[(size_t)s * (D_ / 4)];
        ax += t.x; ay += t.y; az += t.z; aw += t.w;
    }
    float4 r; r.x = ax; r.y = ay; r.z = az; r.w = aw;
    reinterpret_cast<float4*>(g_partial[b][sb])[d4] = r;
}

// ---------------------------------------------------------------------------
// Kernel 2: per batch: cbar -> vbar = cbar@Wv+bv -> LayerNorm -> row = n@Wout+bout
// grid B, block 512 (thread d owns output column d).
// ---------------------------------------------------------------------------
__global__ void k_small(const float* __restrict__ pm,
                        const float* __restrict__ Wv,   const float* __restrict__ bv,
                        const float* __restrict__ gamma,const float* __restrict__ beta,
                        const float* __restrict__ Wout, const float* __restrict__ bout) {
    const int b = blockIdx.x;
    const int d = threadIdx.x;                  // 0..511
    __shared__ float s_vec[D_];
    __shared__ float s_red[16];

    // cbar[d] = (sum_sb partial + sum_p pm) / T
    float acc = 0.f;
#pragma unroll 8
    for (int sb = 0; sb < NSB; ++sb) acc += g_partial[b][sb][d];
#pragma unroll
    for (int p = 0; p < P_; ++p)     acc += pm[p * D_ + d];
    s_vec[d] = acc * (1.0f / (float)T_);
    __syncthreads();

    // vbar[d] = bv[d] + sum_k cbar[k] * Wv[k][d]
    float v = bv[d];
#pragma unroll 8
    for (int k = 0; k < D_; ++k) v = fmaf(s_vec[k], Wv[k * D_ + d], v);

    // --- LayerNorm (two-pass block reduction over 512 lanes / 16 warps) ---
    const int lane = d & 31, wid = d >> 5;
    // pass 1: mean
    float s = v;
#pragma unroll
    for (int o = 16; o; o >>= 1) s += __shfl_down_sync(0xffffffffu, s, o);
    if (lane == 0) s_red[wid] = s;
    __syncthreads();
    if (wid == 0) {
        float t = s_red[lane & 15];
#pragma unroll
        for (int o = 8; o; o >>= 1) t += __shfl_down_sync(0xffffffffu, t, o);
        if (lane == 0) s_red[0] = t * (1.0f / (float)D_);
    }
    __syncthreads();
    const float mu = s_red[0];
    __syncthreads();
    // pass 2: variance
    float dv = v - mu;
    float q = dv * dv;
#pragma unroll
    for (int o = 16; o; o >>= 1) q += __shfl_down_sync(0xffffffffu, q, o);
    if (lane == 0) s_red[wid] = q;
    __syncthreads();
    if (wid == 0) {
        float t = s_red[lane & 15];
#pragma unroll
        for (int o = 8; o; o >>= 1) t += __shfl_down_sync(0xffffffffu, t, o);
        if (lane == 0) s_red[0] = t * (1.0f / (float)D_);
    }
    __syncthreads();
    const float var = s_red[0];
    const float normed = dv * rsqrtf(var + EPS_) * gamma[d] + beta[d];
    __syncthreads();               // s_vec reuse
    s_vec[d] = normed;
    __syncthreads();

    // row[d] = bout[d] + sum_k normed[k] * Wout[k][d]
    float o = bout[d];
#pragma unroll 8
    for (int k = 0; k < D_; ++k) o = fmaf(s_vec[k], Wout[k * D_ + d], o);
    g_row[b][d] = o;
}

// ---------------------------------------------------------------------------
// Kernel 3: broadcast row[b] to out[b, t, :] for all t.
// grid (T/32, B) = (257, 4), block 512, float4 stores; each thread's shared
// source element is loop-invariant (register-resident after first read).
// ---------------------------------------------------------------------------
#define BC_ROWS 32
__global__ void k_bcast(float4* __restrict__ out4) {
    __shared__ float4 s_row[D_ / 4];            // 128
    const int b = blockIdx.y;
    if (threadIdx.x < D_ / 4)
        s_row[threadIdx.x] = reinterpret_cast<const float4*>(g_row[b])[threadIdx.x];
    __syncthreads();
    const size_t base = ((size_t)b * T_ + (size_t)blockIdx.x * BC_ROWS) * (D_ / 4);
    // 32 rows * 128 float4 = 4096 float4 per block; 512 threads -> 8 stores
    const float4 v = s_row[threadIdx.x & (D_ / 4 - 1)];
#pragma unroll
    for (int i = 0; i < 8; ++i)
        out4[base + (size_t)i * 512 + threadIdx.x] = v;
}

// ---------------------------------------------------------------------------
extern "C" void kernel_launch(void* const* d_in, const int* in_sizes, int n_in,
                              void* d_out, int out_size) {
    // metadata order: x, persistent_memory, Wk, bk, Wv, bv, Wq, bq, gamma, beta, Wout, bout
    const float* x     = (const float*)d_in[0];
    const float* pm    = (const float*)d_in[1];
    const float* Wv    = (const float*)d_in[4];
    const float* bv    = (const float*)d_in[5];
    const float* gamma = (const float*)d_in[8];
    const float* beta  = (const float*)d_in[9];
    const float* Wout  = (const float*)d_in[10];
    const float* bout  = (const float*)d_in[11];
    float* out = (float*)d_out;

    dim3 g1(NSB, B_);
    k_reduce<<<g1, 128>>>(reinterpret_cast<const float4*>(x));

    k_small<<<B_, D_>>>(pm, Wv, bv, gamma, beta, Wout, bout);

    dim3 g3(T_ / BC_ROWS, B_);
    k_bcast<<<g3, 512>>>(reinterpret_cast<float4*>(out));
}

// round 14
// speedup vs baseline: 1.9984x; 1.9984x over previous
#include <cuda_runtime.h>

// Problem constants
#define B_   4
#define S_   8192
#define D_   512
#define P_   32
#define T_   (P_ + S_)          // 8224
#define EPS_ 1e-5f

#define NSB  512                 // s-blocks per batch for the reduction
#define ROWS_PER_SB (S_ / NSB)   // 16
#define NSLC 8                   // second-level slices (also gemv blocks per batch)

// Scratch (allocation-free rule: __device__ globals)
__device__ __align__(16) float g_partial[B_][NSB][D_];   // 4 MB
__device__ __align__(16) float g_c2[B_][NSLC][D_];       // 64 KB (slice sums incl. pm)
__device__ __align__(16) float g_vbar[B_][D_];           // 8 KB
__device__ __align__(16) float g_row[B_][D_];            // 8 KB

// ---------------------------------------------------------------------------
// Kernel 1: column-sum of x over 16 rows.  grid (NSB, B), block 128.
// Each thread owns one float4 column of D. 2048 blocks -> high occupancy.
// ---------------------------------------------------------------------------
__global__ void k_reduce(const float4* __restrict__ x4) {
    const int b  = blockIdx.y;
    const int sb = blockIdx.x;
    const int d4 = threadIdx.x;                 // 0..127
    const float4* p = x4 + ((size_t)b * S_ + (size_t)sb * ROWS_PER_SB) * (D_ / 4) + d4;
    float ax = 0.f, ay = 0.f, az = 0.f, aw = 0.f;
#pragma unroll
    for (int s = 0; s < ROWS_PER_SB; ++s) {
        float4 t = p[(size_t)s * (D_ / 4)];
        ax += t.x; ay += t.y; az += t.z; aw += t.w;
    }
    float4 r; r.x = ax; r.y = ay; r.z = az; r.w = aw;
    reinterpret_cast<float4*>(g_partial[b][sb])[d4] = r;
}

// ---------------------------------------------------------------------------
// Kernel 2: second-level tree sum. grid (NSLC, B), block 128.
// Slice s sums partials sb in [64s,64s+64) plus pm rows [4s,4s+4).
// ---------------------------------------------------------------------------
__global__ void k_cbar(const float4* __restrict__ pm4) {
    const int b  = blockIdx.y;
    const int sl = blockIdx.x;
    const int d4 = threadIdx.x;
    const int SB_PER = NSB / NSLC;              // 64
    const int PM_PER = P_ / NSLC;               // 4
    float ax = 0.f, ay = 0.f, az = 0.f, aw = 0.f;
    const float4* pp = reinterpret_cast<const float4*>(g_partial[b][sl * SB_PER]) + d4;
#pragma unroll 8
    for (int i = 0; i < SB_PER; ++i) {
        float4 t = pp[(size_t)i * (D_ / 4)];
        ax += t.x; ay += t.y; az += t.z; aw += t.w;
    }
#pragma unroll
    for (int j = 0; j < PM_PER; ++j) {
        float4 t = pm4[(size_t)(sl * PM_PER + j) * (D_ / 4) + d4];
        ax += t.x; ay += t.y; az += t.z; aw += t.w;
    }
    float4 r; r.x = ax; r.y = ay; r.z = az; r.w = aw;
    reinterpret_cast<float4*>(g_c2[b][sl])[d4] = r;
}

// ---------------------------------------------------------------------------
// Kernel 3: vbar slice = cbar @ Wv + bv.  grid (NSLC, B), block 256.
// Block computes 64 outputs; 4 k-groups of 128 each, smem-reduced.
// ---------------------------------------------------------------------------
__global__ void k_gemv1(const float* __restrict__ Wv, const float* __restrict__ bv) {
    const int b  = blockIdx.y;
    const int j0 = blockIdx.x * 64;
    const int t  = threadIdx.x;                 // 0..255
    __shared__ float s_cbar[D_];
    __shared__ float s_red[4][64];

    // cbar[d] = (sum of 8 slice sums) / T   (2 d's per thread)
#pragma unroll
    for (int r = 0; r < 2; ++r) {
        const int d = t + r * 256;
        float a = 0.f;
#pragma unroll
        for (int s = 0; s < NSLC; ++s) a += g_c2[b][s][d];
        s_cbar[d] = a * (1.0f / (float)T_);
    }
    __syncthreads();

    const int j = t & 63, g = t >> 6;           // output, k-group
    float acc = 0.f;
    const float* w = Wv + (size_t)(g * 128) * D_ + j0 + j;
#pragma unroll 8
    for (int k = 0; k < 128; ++k)
        acc = fmaf(s_cbar[g * 128 + k], w[(size_t)k * D_], acc);
    s_red[g][j] = acc;
    __syncthreads();
    if (t < 64)
        g_vbar[b][j0 + t] = s_red[0][t] + s_red[1][t] + s_red[2][t] + s_red[3][t] + bv[j0 + t];
}

// ---------------------------------------------------------------------------
// Kernel 4: LayerNorm (stats recomputed per block) then slice of @Wout + bout.
// grid (NSLC, B), block 256.
// ---------------------------------------------------------------------------
__global__ void k_gemv2(const float* __restrict__ Wout, const float* __restrict__ bout,
                        const float* __restrict__ gamma, const float* __restrict__ beta) {
    const int b  = blockIdx.y;
    const int j0 = blockIdx.x * 64;
    const int t  = threadIdx.x;
    __shared__ float s_nrm[D_];
    __shared__ float s_r[8];

    // load vbar (2 per thread) and block-reduce mean
    const float v0 = g_vbar[b][t], v1 = g_vbar[b][t + 256];
    const int lane = t & 31, wid = t >> 5;
    float s = v0 + v1;
#pragma unroll
    for (int o = 16; o; o >>= 1) s += __shfl_down_sync(0xffffffffu, s, o);
    if (lane == 0) s_r[wid] = s;
    __syncthreads();
    if (t == 0) {
        float a = 0.f;
#pragma unroll
        for (int w = 0; w < 8; ++w) a += s_r[w];
        s_r[0] = a * (1.0f / (float)D_);
    }
    __syncthreads();
    const float mu = s_r[0];
    __syncthreads();
    // variance
    float q = (v0 - mu) * (v0 - mu) + (v1 - mu) * (v1 - mu);
#pragma unroll
    for (int o = 16; o; o >>= 1) q += __shfl_down_sync(0xffffffffu, q, o);
    if (lane == 0) s_r[wid] = q;
    __syncthreads();
    if (t == 0) {
        float a = 0.f;
#pragma unroll
        for (int w = 0; w < 8; ++w) a += s_r[w];
        s_r[0] = a * (1.0f / (float)D_);
    }
    __syncthreads();
    const float rs = rsqrtf(s_r[0] + EPS_);
    s_nrm[t]       = (v0 - mu) * rs * gamma[t]       + beta[t];
    s_nrm[t + 256] = (v1 - mu) * rs * gamma[t + 256] + beta[t + 256];
    __syncthreads();

    __shared__ float s_red[4][64];
    const int j = t & 63, g = t >> 6;
    float acc = 0.f;
    const float* w = Wout + (size_t)(g * 128) * D_ + j0 + j;
#pragma unroll 8
    for (int k = 0; k < 128; ++k)
        acc = fmaf(s_nrm[g * 128 + k], w[(size_t)k * D_], acc);
    s_red[g][j] = acc;
    __syncthreads();
    if (t < 64)
        g_row[b][j0 + t] = s_red[0][t] + s_red[1][t] + s_red[2][t] + s_red[3][t] + bout[j0 + t];
}

// ---------------------------------------------------------------------------
// Kernel 5: broadcast row[b] to out[b, t, :].  grid (257, 4), block 512.
// ---------------------------------------------------------------------------
#define BC_ROWS 32
__global__ void k_bcast(float4* __restrict__ out4) {
    __shared__ float4 s_row[D_ / 4];
    const int b = blockIdx.y;
    if (threadIdx.x < D_ / 4)
        s_row[threadIdx.x] = reinterpret_cast<const float4*>(g_row[b])[threadIdx.x];
    __syncthreads();
    const size_t base = ((size_t)b * T_ + (size_t)blockIdx.x * BC_ROWS) * (D_ / 4);
    const float4 v = s_row[threadIdx.x & (D_ / 4 - 1)];
#pragma unroll
    for (int i = 0; i < 8; ++i)
        out4[base + (size_t)i * 512 + threadIdx.x] = v;
}

// ---------------------------------------------------------------------------
extern "C" void kernel_launch(void* const* d_in, const int* in_sizes, int n_in,
                              void* d_out, int out_size) {
    // metadata order: x, persistent_memory, Wk, bk, Wv, bv, Wq, bq, gamma, beta, Wout, bout
    const float* x     = (const float*)d_in[0];
    const float* pm    = (const float*)d_in[1];
    const float* Wv    = (const float*)d_in[4];
    const float* bv    = (const float*)d_in[5];
    const float* gamma = (const float*)d_in[8];
    const float* beta  = (const float*)d_in[9];
    const float* Wout  = (const float*)d_in[10];
    const float* bout  = (const float*)d_in[11];
    float* out = (float*)d_out;

    dim3 g1(NSB, B_);
    k_reduce<<<g1, 128>>>(reinterpret_cast<const float4*>(x));

    dim3 g2(NSLC, B_);
    k_cbar<<<g2, 128>>>(reinterpret_cast<const float4*>(pm));
    k_gemv1<<<g2, 256>>>(Wv, bv);
    k_gemv2<<<g2, 256>>>(Wout, bout, gamma, beta);

    dim3 g5(T_ / BC_ROWS, B_);
    k_bcast<<<g5, 512>>>(reinterpret_cast<float4*>(out));
}

// round 15
// speedup vs baseline: 2.2185x; 1.1101x over previous
#include <cuda_runtime.h>

// Problem constants
#define B_   4
#define S_   8192
#define D_   512
#define P_   32
#define T_   (P_ + S_)          // 8224
#define EPS_ 1e-5f

#define NSB  512                 // s-blocks per batch for the reduction
#define ROWS_PER_SB (S_ / NSB)   // 16
#define NSLC 8                   // second-level slices / gemv col-blocks per batch

// Scratch (allocation-free rule: __device__ globals)
__device__ __align__(16) float g_partial[B_][NSB][D_];   // 4 MB
__device__ __align__(16) float g_c2[B_][NSLC][D_];       // 64 KB
__device__ __align__(16) float g_vbar[B_][D_];           // 8 KB
__device__ __align__(16) float g_row[B_][D_];            // 8 KB

// ---------------------------------------------------------------------------
// Kernel 1: column-sum of x over 16 rows.  grid (NSB, B), block 128.
// ---------------------------------------------------------------------------
__global__ void k_reduce(const float4* __restrict__ x4) {
    const int b  = blockIdx.y;
    const int sb = blockIdx.x;
    const int d4 = threadIdx.x;                 // 0..127
    const float4* p = x4 + ((size_t)b * S_ + (size_t)sb * ROWS_PER_SB) * (D_ / 4) + d4;
    float ax = 0.f, ay = 0.f, az = 0.f, aw = 0.f;
#pragma unroll
    for (int s = 0; s < ROWS_PER_SB; ++s) {
        float4 t = p[(size_t)s * (D_ / 4)];
        ax += t.x; ay += t.y; az += t.z; aw += t.w;
    }
    float4 r; r.x = ax; r.y = ay; r.z = az; r.w = aw;
    reinterpret_cast<float4*>(g_partial[b][sb])[d4] = r;
}

// ---------------------------------------------------------------------------
// Kernel 2: second-level tree sum. grid (NSLC, B), block 128.
// ---------------------------------------------------------------------------
__global__ void k_cbar(const float4* __restrict__ pm4) {
    const int b  = blockIdx.y;
    const int sl = blockIdx.x;
    const int d4 = threadIdx.x;
    const int SB_PER = NSB / NSLC;              // 64
    const int PM_PER = P_ / NSLC;               // 4
    float ax = 0.f, ay = 0.f, az = 0.f, aw = 0.f;
    const float4* pp = reinterpret_cast<const float4*>(g_partial[b][sl * SB_PER]) + d4;
#pragma unroll 8
    for (int i = 0; i < SB_PER; ++i) {
        float4 t = pp[(size_t)i * (D_ / 4)];
        ax += t.x; ay += t.y; az += t.z; aw += t.w;
    }
#pragma unroll
    for (int j = 0; j < PM_PER; ++j) {
        float4 t = pm4[(size_t)(sl * PM_PER + j) * (D_ / 4) + d4];
        ax += t.x; ay += t.y; az += t.z; aw += t.w;
    }
    float4 r; r.x = ax; r.y = ay; r.z = az; r.w = aw;
    reinterpret_cast<float4*>(g_c2[b][sl])[d4] = r;
}

// ---------------------------------------------------------------------------
// MLP-optimized GEMV core: block computes 64 output cols (one float4 x 16
// j4-groups) from a 512-deep K using 16 kg-strips of 32 k each.
// Each thread: 32 independent LDG.128 into 4 independent accumulators.
// ---------------------------------------------------------------------------
__device__ __forceinline__ void gemv_core(const float* __restrict__ W,
                                          const float* __restrict__ s_in,
                                          float s_part[16][64],
                                          int j0, int t) {
    const int j4 = t & 15;                       // float4 column group
    const int kg = t >> 4;                       // k-strip index (16 strips)
    const float4* w4 = reinterpret_cast<const float4*>(W) + (j0 >> 2) + j4;
    float4 acc; acc.x = acc.y = acc.z = acc.w = 0.f;
#pragma unroll 16
    for (int i = 0; i < 32; ++i) {
        const int k = kg * 32 + i;
        const float4 w = w4[(size_t)k * (D_ / 4)];
        const float s = s_in[k];
        acc.x = fmaf(s, w.x, acc.x);
        acc.y = fmaf(s, w.y, acc.y);
        acc.z = fmaf(s, w.z, acc.z);
        acc.w = fmaf(s, w.w, acc.w);
    }
    *reinterpret_cast<float4*>(&s_part[kg][j4 * 4]) = acc;
}

// ---------------------------------------------------------------------------
// Kernel 3: vbar slice = cbar @ Wv + bv.  grid (NSLC, B), block 256.
// ---------------------------------------------------------------------------
__global__ void k_gemv1(const float* __restrict__ Wv, const float* __restrict__ bv) {
    const int b  = blockIdx.y;
    const int j0 = blockIdx.x * 64;
    const int t  = threadIdx.x;                  // 0..255
    __shared__ float s_cbar[D_];
    __shared__ float s_part[16][64];

    // cbar[d] = (sum of 8 slice sums) / T  (2 d's per thread)
#pragma unroll
    for (int r = 0; r < 2; ++r) {
        const int d = t + r * 256;
        float a = 0.f;
#pragma unroll
        for (int s = 0; s < NSLC; ++s) a += g_c2[b][s][d];
        s_cbar[d] = a * (1.0f / (float)T_);
    }
    __syncthreads();

    gemv_core(Wv, s_cbar, s_part, j0, t);
    __syncthreads();

    if (t < 64) {
        float a = bv[j0 + t];
#pragma unroll
        for (int kg = 0; kg < 16; ++kg) a += s_part[kg][t];
        g_vbar[b][j0 + t] = a;
    }
}

// ---------------------------------------------------------------------------
// Kernel 4: LayerNorm (stats per block, redundant but deterministic), then
// row slice = normed @ Wout + bout.  grid (NSLC, B), block 256.
// ---------------------------------------------------------------------------
__global__ void k_gemv2(const float* __restrict__ Wout, const float* __restrict__ bout,
                        const float* __restrict__ gamma, const float* __restrict__ beta) {
    const int b  = blockIdx.y;
    const int j0 = blockIdx.x * 64;
    const int t  = threadIdx.x;
    __shared__ float s_nrm[D_];
    __shared__ float s_r[8];
    __shared__ float s_part[16][64];

    // load vbar (2 per thread) + block-reduce mean
    const float v0 = g_vbar[b][t], v1 = g_vbar[b][t + 256];
    const int lane = t & 31, wid = t >> 5;
    float s = v0 + v1;
#pragma unroll
    for (int o = 16; o; o >>= 1) s += __shfl_down_sync(0xffffffffu, s, o);
    if (lane == 0) s_r[wid] = s;
    __syncthreads();
    if (t == 0) {
        float a = 0.f;
#pragma unroll
        for (int w = 0; w < 8; ++w) a += s_r[w];
        s_r[0] = a * (1.0f / (float)D_);
    }
    __syncthreads();
    const float mu = s_r[0];
    __syncthreads();
    // variance
    float q = (v0 - mu) * (v0 - mu) + (v1 - mu) * (v1 - mu);
#pragma unroll
    for (int o = 16; o; o >>= 1) q += __shfl_down_sync(0xffffffffu, q, o);
    if (lane == 0) s_r[wid] = q;
    __syncthreads();
    if (t == 0) {
        float a = 0.f;
#pragma unroll
        for (int w = 0; w < 8; ++w) a += s_r[w];
        s_r[0] = a * (1.0f / (float)D_);
    }
    __syncthreads();
    const float rs = rsqrtf(s_r[0] + EPS_);
    s_nrm[t]       = (v0 - mu) * rs * gamma[t]       + beta[t];
    s_nrm[t + 256] = (v1 - mu) * rs * gamma[t + 256] + beta[t + 256];
    __syncthreads();

    gemv_core(Wout, s_nrm, s_part, j0, t);
    __syncthreads();

    if (t < 64) {
        float a = bout[j0 + t];
#pragma unroll
        for (int kg = 0; kg < 16; ++kg) a += s_part[kg][t];
        g_row[b][j0 + t] = a;
    }
}

// ---------------------------------------------------------------------------
// Kernel 5: broadcast row[b] to out[b, t, :].  grid (257, 4), block 512.
// ---------------------------------------------------------------------------
#define BC_ROWS 32
__global__ void k_bcast(float4* __restrict__ out4) {
    __shared__ float4 s_row[D_ / 4];
    const int b = blockIdx.y;
    if (threadIdx.x < D_ / 4)
        s_row[threadIdx.x] = reinterpret_cast<const float4*>(g_row[b])[threadIdx.x];
    __syncthreads();
    const size_t base = ((size_t)b * T_ + (size_t)blockIdx.x * BC_ROWS) * (D_ / 4);
    const float4 v = s_row[threadIdx.x & (D_ / 4 - 1)];
#pragma unroll
    for (int i = 0; i < 8; ++i)
        out4[base + (size_t)i * 512 + threadIdx.x] = v;
}

// ---------------------------------------------------------------------------
extern "C" void kernel_launch(void* const* d_in, const int* in_sizes, int n_in,
                              void* d_out, int out_size) {
    // metadata order: x, persistent_memory, Wk, bk, Wv, bv, Wq, bq, gamma, beta, Wout, bout
    const float* x     = (const float*)d_in[0];
    const float* pm    = (const float*)d_in[1];
    const float* Wv    = (const float*)d_in[4];
    const float* bv    = (const float*)d_in[5];
    const float* gamma = (const float*)d_in[8];
    const float* beta  = (const float*)d_in[9];
    const float* Wout  = (const float*)d_in[10];
    const float* bout  = (const float*)d_in[11];
    float* out = (float*)d_out;

    dim3 g1(NSB, B_);
    k_reduce<<<g1, 128>>>(reinterpret_cast<const float4*>(x));

    dim3 g2(NSLC, B_);
    k_cbar<<<g2, 128>>>(reinterpret_cast<const float4*>(pm));
    k_gemv1<<<g2, 256>>>(Wv, bv);
    k_gemv2<<<g2, 256>>>(Wout, bout, gamma, beta);

    dim3 g5(T_ / BC_ROWS, B_);
    k_bcast<<<g5, 512>>>(reinterpret_cast<float4*>(out));
}